// round 7
// baseline (speedup 1.0000x reference)
#include <cuda_runtime.h>

// LightweightConv: depthwise temporal conv with per-head softmax weights.
// B=16, T=4000, C=512, H=8, K=31, PAD=15.
// out[b,t,c] = sum_k softmax(w)[c%8][k] * x[b, t-15+k, c] + bias[c%8]
//
// R7: cp.async (LDGSTS) -> SMEM -> LDS pipeline. x rows are staged in 8-row
// chunks through a 3-buffer SMEM ring, so FFMA2s never wait on DRAM
// scoreboards. zfill (src-size 0) handles t<0 / t>=T uniformly: one path.

#define B_ 16
#define T_ 4000
#define C_ 512
#define H_ 8
#define K_ 31
#define PAD_ 15
#define TT 24          // t-outputs per thread; ceil(4000/24) = 167 t-blocks
#define NROWS (TT + 2 * PAD_)   // 54 input rows per block
#define R_ 8           // rows per chunk
#define D_ 3           // ring buffers
#define NC 7           // chunks (56 rows >= 54)

// Packed (per channel-pair) softmaxed weights and bias.
// Pair type p in [0,4): channels (2p, 2p+1) mod 8 -> heads (2p, 2p+1).
__device__ unsigned long long g_wpair[4][K_];
__device__ unsigned long long g_bpair[4];

__global__ void prep_kernel(const float* __restrict__ w,
                            const float* __restrict__ bias) {
    __shared__ float ws[H_][K_];
    int tid = threadIdx.x;
    if (tid < H_) {
        float m = -3.402823466e38f;
        #pragma unroll
        for (int k = 0; k < K_; k++) m = fmaxf(m, w[tid * K_ + k]);
        float e[K_];
        float s = 0.0f;
        #pragma unroll
        for (int k = 0; k < K_; k++) {
            e[k] = expf(w[tid * K_ + k] - m);
            s += e[k];
        }
        float inv = 1.0f / s;
        #pragma unroll
        for (int k = 0; k < K_; k++) ws[tid][k] = e[k] * inv;
    }
    __syncthreads();
    if (tid < 4 * K_) {
        int p = tid / K_;
        int k = tid % K_;
        float2 v = make_float2(ws[2 * p][k], ws[2 * p + 1][k]);
        g_wpair[p][k] = *reinterpret_cast<unsigned long long*>(&v);
    }
    if (tid < 4) {
        float2 v = make_float2(bias[2 * tid], bias[2 * tid + 1]);
        g_bpair[tid] = *reinterpret_cast<unsigned long long*>(&v);
    }
}

// Packed fp32x2 FMA (sm_100+): d = a*b + c elementwise on two packed floats.
__device__ __forceinline__ unsigned long long ffma2(unsigned long long a,
                                                    unsigned long long b,
                                                    unsigned long long c) {
    unsigned long long d;
    asm("fma.rn.f32x2 %0, %1, %2, %3;" : "=l"(d) : "l"(a), "l"(b), "l"(c));
    return d;
}

// Streaming 8B store (evict-first: output is never re-read; protect L2 halo).
__device__ __forceinline__ void stcs8(float* a, unsigned long long v) {
    asm volatile("st.global.cs.b64 [%0], %1;" :: "l"(a), "l"(v));
}

__device__ __forceinline__ unsigned smem_u32(const void* p) {
    unsigned a;
    asm("{ .reg .u64 t; cvta.to.shared.u64 t, %1; cvt.u32.u64 %0, t; }"
        : "=r"(a) : "l"(p));
    return a;
}

__global__ void __launch_bounds__(256, 2)
conv_kernel(const float* __restrict__ x, float* __restrict__ out) {
    __shared__ float s_x[D_][R_][C_];   // 3 * 8 * 2KB = 48KB

    const int tid = threadIdx.x;          // 0..255
    const int c0 = tid << 1;              // channels c0, c0+1 (contiguous)
    const int p = tid & 3;                // pair type: heads (2p, 2p+1)
    const int b = blockIdx.y;
    const int t0 = blockIdx.x * TT;

    // cp.async slice for this thread: 4 pieces of 16B per 16KB chunk.
    // piece m: row = 2m + (tid>>7), float col = (tid&127)*4.
    const int half = tid >> 7;
    const int colf = (tid & 127) << 2;
    const float* xb = x + (size_t)b * T_ * C_;

    // Weights resident in registers (proven best in R1-R6).
    unsigned long long wk[K_];
    #pragma unroll
    for (int k = 0; k < K_; k++) wk[k] = g_wpair[p][k];

    unsigned long long acc[TT];
    {
        const unsigned long long bb = g_bpair[p];
        #pragma unroll
        for (int j = 0; j < TT; j++) acc[j] = bb;
    }

    // Issue one chunk (or an empty group past the end, to keep the
    // wait_group accounting constant).
    auto issue = [&](int c) {
        if (c < NC) {
            #pragma unroll
            for (int m = 0; m < 4; m++) {
                const int row = 2 * m + half;
                const int t = t0 - PAD_ + c * R_ + row;
                const int zf = (t >= 0 && t < T_) ? 16 : 0;
                const int tc = t < 0 ? 0 : (t >= T_ ? T_ - 1 : t);
                const float* src = xb + (size_t)tc * C_ + colf;
                const unsigned dst = smem_u32(&s_x[c % D_][row][colf]);
                asm volatile("cp.async.cg.shared.global [%0], [%1], 16, %2;"
                             :: "r"(dst), "l"(src), "r"(zf));
            }
        }
        asm volatile("cp.async.commit_group;" ::: "memory");
    };

    issue(0);
    issue(1);
    issue(2);

    #pragma unroll
    for (int c = 0; c < NC; c++) {
        asm volatile("cp.async.wait_group 2;" ::: "memory");
        __syncthreads();                       // chunk c visible to all warps

        #pragma unroll
        for (int ri = 0; ri < R_; ri++) {
            const int i = c * R_ + ri;         // global row index, < NROWS used
            if (i < NROWS) {
                const unsigned long long xv =
                    *reinterpret_cast<const unsigned long long*>(
                        &s_x[c % D_][ri][c0]);
                #pragma unroll
                for (int j = 0; j < TT; j++) {
                    if (i - j >= 0 && i - j < K_)   // constant-folds
                        acc[j] = ffma2(wk[i - j], xv, acc[j]);
                }
            }
        }

        __syncthreads();                       // buffer c%D free to overwrite
        issue(c + D_);
    }

    float* op = out + ((size_t)b * T_ + t0) * C_ + c0;
    #pragma unroll
    for (int j = 0; j < TT; j++)
        if (t0 + j < T_)                       // tail block guard
            stcs8(op + (size_t)j * C_, acc[j]);
}

extern "C" void kernel_launch(void* const* d_in, const int* in_sizes, int n_in,
                              void* d_out, int out_size) {
    const float* x    = (const float*)d_in[0];  // (B, T, C)
    const float* w    = (const float*)d_in[1];  // (H, 1, K)
    const float* bias = (const float*)d_in[2];  // (H,)
    float* out = (float*)d_out;                 // (B, T, C)

    prep_kernel<<<1, 128>>>(w, bias);

    dim3 grid((T_ + TT - 1) / TT, B_);
    conv_kernel<<<grid, 256>>>(x, out);
}

// round 8
// speedup vs baseline: 1.1828x; 1.1828x over previous
#include <cuda_runtime.h>

// LightweightConv: depthwise temporal conv with per-head softmax weights.
// B=16, T=4000, C=512, H=8, K=31, PAD=15.
// out[b,t,c] = sum_k softmax(w)[c%8][k] * x[b, t-15+k, c] + bias[c%8]
//
// R8: R6 (best, 49.0us: TT=24, weights resident, streaming stores) plus a
// 4-instruction prefetch.global.L2 prologue warming the block's whole 108KB
// input span, so first-touch loads see L2-hit latency instead of DRAM.

#define B_ 16
#define T_ 4000
#define C_ 512
#define H_ 8
#define K_ 31
#define PAD_ 15
#define TT 24   // t-outputs per thread; ceil(4000/24) = 167 blocks in t

// Packed (per channel-pair) softmaxed weights and bias.
// Pair type p in [0,4): channels (2p, 2p+1) mod 8 -> heads (2p, 2p+1).
__device__ unsigned long long g_wpair[4][K_];
__device__ unsigned long long g_bpair[4];

__global__ void prep_kernel(const float* __restrict__ w,
                            const float* __restrict__ bias) {
    __shared__ float ws[H_][K_];
    int tid = threadIdx.x;
    if (tid < H_) {
        float m = -3.402823466e38f;
        #pragma unroll
        for (int k = 0; k < K_; k++) m = fmaxf(m, w[tid * K_ + k]);
        float e[K_];
        float s = 0.0f;
        #pragma unroll
        for (int k = 0; k < K_; k++) {
            e[k] = expf(w[tid * K_ + k] - m);
            s += e[k];
        }
        float inv = 1.0f / s;
        #pragma unroll
        for (int k = 0; k < K_; k++) ws[tid][k] = e[k] * inv;
    }
    __syncthreads();
    if (tid < 4 * K_) {
        int p = tid / K_;
        int k = tid % K_;
        float2 v = make_float2(ws[2 * p][k], ws[2 * p + 1][k]);
        g_wpair[p][k] = *reinterpret_cast<unsigned long long*>(&v);
    }
    if (tid < 4) {
        float2 v = make_float2(bias[2 * tid], bias[2 * tid + 1]);
        g_bpair[tid] = *reinterpret_cast<unsigned long long*>(&v);
    }
}

// Packed fp32x2 FMA (sm_100+): d = a*b + c elementwise on two packed floats.
__device__ __forceinline__ unsigned long long ffma2(unsigned long long a,
                                                    unsigned long long b,
                                                    unsigned long long c) {
    unsigned long long d;
    asm("fma.rn.f32x2 %0, %1, %2, %3;" : "=l"(d) : "l"(a), "l"(b), "l"(c));
    return d;
}

// Streaming 8B store (evict-first: output is never re-read; protect L2 halo).
__device__ __forceinline__ void stcs8(float* a, unsigned long long v) {
    asm volatile("st.global.cs.b64 [%0], %1;" :: "l"(a), "l"(v));
}

__device__ __forceinline__ void pf_l2(const void* a) {
    asm volatile("prefetch.global.L2 [%0];" :: "l"(a));
}

__global__ void __launch_bounds__(256, 2)
conv_kernel(const float* __restrict__ x, float* __restrict__ out) {
    const int tid = threadIdx.x;          // 0..255
    const int c0 = tid << 1;              // channels c0, c0+1 (contiguous)
    const int p = tid & 3;                // pair type: heads (2p, 2p+1)
    const int b = blockIdx.y;
    const int t0 = blockIdx.x * TT;

    // --- L2 prefetch prologue: warm this block's whole input span. ---
    // Rows t0-PAD .. t0-PAD+TT+2*PAD-1 are contiguous: (TT+30)*2KB = 108KB.
    {
        const int tlo = max(t0 - PAD_, 0);
        const int thi = min(t0 - PAD_ + TT + 2 * PAD_, T_);   // exclusive
        const char* base = reinterpret_cast<const char*>(
            x + ((size_t)b * T_ + tlo) * C_);
        const int nbytes = (thi - tlo) * (int)(C_ * sizeof(float));
        #pragma unroll
        for (int r = 0; r < 4; r++) {
            const int off = (tid + 256 * r) << 7;              // *128B
            if (off < nbytes) pf_l2(base + off);
        }
    }

    // Weights for this channel pair (packed), resident in registers.
    unsigned long long wk[K_];
    #pragma unroll
    for (int k = 0; k < K_; k++) wk[k] = g_wpair[p][k];

    const unsigned long long bb = g_bpair[p];

    unsigned long long acc[TT];
    #pragma unroll
    for (int j = 0; j < TT; j++) acc[j] = bb;

    const float* xp = x + ((size_t)b * T_) * C_ + c0;

    if (t0 >= PAD_ && t0 + TT + PAD_ <= T_) {
        // Interior fast path: no boundary predicates.
        const float* xq = xp + (size_t)(t0 - PAD_) * C_;
        #pragma unroll
        for (int i = 0; i < TT + 2 * PAD_; i++) {
            const unsigned long long xv =
                *reinterpret_cast<const unsigned long long*>(xq + (size_t)i * C_);
            #pragma unroll
            for (int j = 0; j < TT; j++) {
                if (i - j >= 0 && i - j < K_)   // constant-folds after unroll
                    acc[j] = ffma2(wk[i - j], xv, acc[j]);
            }
        }
        float* op = out + ((size_t)b * T_ + t0) * C_ + c0;
        #pragma unroll
        for (int j = 0; j < TT; j++)
            stcs8(op + (size_t)j * C_, acc[j]);
    } else {
        // Boundary path: zero-padded loads, guarded stores (covers tail block).
        #pragma unroll
        for (int i = 0; i < TT + 2 * PAD_; i++) {
            const int t = t0 - PAD_ + i;
            unsigned long long xv = 0ull;
            if (t >= 0 && t < T_)
                xv = *reinterpret_cast<const unsigned long long*>(xp + (size_t)t * C_);
            #pragma unroll
            for (int j = 0; j < TT; j++) {
                if (i - j >= 0 && i - j < K_)
                    acc[j] = ffma2(wk[i - j], xv, acc[j]);
            }
        }
        float* op = out + ((size_t)b * T_ + t0) * C_ + c0;
        #pragma unroll
        for (int j = 0; j < TT; j++)
            if (t0 + j < T_)
                stcs8(op + (size_t)j * C_, acc[j]);
    }
}

extern "C" void kernel_launch(void* const* d_in, const int* in_sizes, int n_in,
                              void* d_out, int out_size) {
    const float* x    = (const float*)d_in[0];  // (B, T, C)
    const float* w    = (const float*)d_in[1];  // (H, 1, K)
    const float* bias = (const float*)d_in[2];  // (H,)
    float* out = (float*)d_out;                 // (B, T, C)

    prep_kernel<<<1, 128>>>(w, bias);

    dim3 grid((T_ + TT - 1) / TT, B_);
    conv_kernel<<<grid, 256>>>(x, out);
}